// round 14
// baseline (speedup 1.0000x reference)
#include <cuda_runtime.h>
#include <math.h>

#define BATCH 8
#define SEQ 512
#define HID 768
#define NHEAD 12
#define DHEAD 64
#define NLAYER 12
#define FFDIM 3072
#define SPAN 256
#define TSPAN 512
#define EPS 1e-7f

// ---------------- scratch (static device globals; no allocs allowed) ----------------
__device__ float g_h  [BATCH*SEQ*HID];
__device__ float g_q  [BATCH*SEQ*HID];
__device__ float g_k  [BATCH*SEQ*HID];
__device__ float g_v  [BATCH*SEQ*HID];
__device__ float g_tmp[BATCH*SEQ*HID];
__device__ float g_h1 [BATCH*SEQ*HID];
__device__ float g_ctx[BATCH*SEQ*HID];
__device__ float g_ff [BATCH*SEQ*FFDIM];
__device__ float g_qk [(size_t)BATCH*NHEAD*SEQ*SEQ];
__device__ float g_c2p[(size_t)BATCH*NHEAD*SEQ*TSPAN];   // [q, m] per (b,h)
__device__ float g_p2c[(size_t)BATCH*NHEAD*TSPAN*SEQ];   // TRANSPOSED: [m, k] per (b,h)
__device__ float g_posk[TSPAN*HID];
__device__ float g_posq[TSPAN*HID];
__device__ int   g_c2pidx[SEQ*SEQ];   // p2cidx[k,q] == c2pidx[q,k] (DeBERTa identity)

// ---------------- tf32 helpers ----------------
__device__ __forceinline__ unsigned f2tf32(float x) {
    unsigned r;
    asm("cvt.rna.tf32.f32 %0, %1;" : "=r"(r) : "f"(x));
    return r;
}

__device__ __forceinline__ void mma8(float* c, const unsigned* a, const unsigned* b) {
    asm volatile(
        "mma.sync.aligned.m16n8k8.row.col.f32.tf32.tf32.f32 "
        "{%0,%1,%2,%3},{%4,%5,%6,%7},{%8,%9},{%0,%1,%2,%3};"
        : "+f"(c[0]), "+f"(c[1]), "+f"(c[2]), "+f"(c[3])
        : "r"(a[0]), "r"(a[1]), "r"(a[2]), "r"(a[3]), "r"(b[0]), "r"(b[1]));
}

// pack one fp32 into hi/lo tf32 pair
__device__ __forceinline__ void split2(float x, float& hi, float& lo) {
    unsigned hb = f2tf32(x);
    hi = __uint_as_float(hb);
    lo = __uint_as_float(f2tf32(x - hi));
}

// ---------------- relative position bucketing ----------------
__global__ void build_idx_kernel() {
    int idx = blockIdx.x * blockDim.x + threadIdx.x;
    if (idx >= SEQ * SEQ) return;
    int q = idx / SEQ, k = idx % SEQ;
    int rel = q - k;
    const int mid = SPAN / 2;  // 128
    int sgn = (rel > 0) - (rel < 0);
    double abs_pos = (rel < mid && rel > -mid) ? (double)(mid - 1) : (double)abs(rel);
    int bucket;
    if (abs_pos <= (double)mid) {
        bucket = rel;
    } else {
        double lp = ceil(log(abs_pos / (double)mid) / log(511.0 / (double)mid) * (double)(mid - 1))
                    + (double)mid;
        bucket = (int)(lp * (double)sgn);
    }
    int c2p = bucket + SPAN;  c2p = min(max(c2p, 0), TSPAN - 1);
    g_c2pidx[idx] = c2p;
}

// ---------------- embedding gather ----------------
__global__ void embed_kernel(const float* __restrict__ we, const float* __restrict__ pe,
                             const int* __restrict__ ids, float* __restrict__ out) {
    long i = (long)blockIdx.x * blockDim.x + threadIdx.x;
    if (i >= (long)BATCH * SEQ * HID) return;
    int c = (int)(i % HID);
    long t = i / HID;
    int s = (int)(t % SEQ);
    out[i] = we[(long)ids[t] * HID + c] + pe[(long)s * HID + c];
}

// ---------------- LayerNorm (optional residual, optional mask scaling) ----------------
__global__ __launch_bounds__(256) void ln_kernel(
    const float* __restrict__ x, const float* __restrict__ res,
    const float* __restrict__ g, const float* __restrict__ bta,
    const int* __restrict__ mask, float* __restrict__ out)
{
    int t = blockIdx.x;
    int tid = threadIdx.x;
    __shared__ float sh[HID];
    __shared__ float sred[8];
    __shared__ float s_mu, s_rstd;

    const float* xp = x + (long)t * HID;
    const float* rp = res ? (res + (long)t * HID) : nullptr;

    float s = 0.f;
    for (int i = tid; i < HID; i += 256) {
        float v = xp[i] + (rp ? rp[i] : 0.f);
        sh[i] = v;
        s += v;
    }
    #pragma unroll
    for (int o = 16; o > 0; o >>= 1) s += __shfl_xor_sync(0xffffffffu, s, o);
    if ((tid & 31) == 0) sred[tid >> 5] = s;
    __syncthreads();
    if (tid == 0) {
        float tt = 0.f;
        #pragma unroll
        for (int i = 0; i < 8; i++) tt += sred[i];
        s_mu = tt / (float)HID;
    }
    __syncthreads();
    float mu = s_mu;

    float vs = 0.f;
    for (int i = tid; i < HID; i += 256) { float d = sh[i] - mu; vs += d * d; }
    #pragma unroll
    for (int o = 16; o > 0; o >>= 1) vs += __shfl_xor_sync(0xffffffffu, vs, o);
    if ((tid & 31) == 0) sred[tid >> 5] = vs;
    __syncthreads();
    if (tid == 0) {
        float tt = 0.f;
        #pragma unroll
        for (int i = 0; i < 8; i++) tt += sred[i];
        s_rstd = 1.0f / sqrtf(tt / (float)HID + EPS);
    }
    __syncthreads();
    float rstd = s_rstd;
    float mscale = mask ? (float)mask[t] : 1.0f;

    float* op = out + (long)t * HID;
    for (int i = tid; i < HID; i += 256)
        op[i] = ((sh[i] - mu) * rstd * g[i] + bta[i]) * mscale;
}

// ---------------- dense GEMM via 3xTF32 tensor cores, float4-packed fragments --------
// C[M,N] = A[M,K] @ B[K,N] + bias, optional exact GELU. A row-major (stride K),
// B row-major (stride N). 128x128 CTA tile, 256 threads = 8 warps (2x4), warp tile
// 64x32 (4x4 mma tiles), K-tile 16. hi/lo tf32 split: acc += Ah*Bh + Ah*Bl + Al*Bh.
// Smem packs {hi(k=qd), lo(qd), hi(qd+4), lo(qd+4)} per float4: fragment loads are
// single conflict-free LDS.128.
__device__ __forceinline__ void tf32_gemm_tile(
    const float* __restrict__ A, const float* __restrict__ B,
    const float* __restrict__ bias, float* __restrict__ C,
    int N, int K, int fuse_gelu, int bx, int by,
    float4* PA, float4* PB)   // each [2][128][4] float4 = 16 KB
{
    int tid = threadIdx.x;
    int lane = tid & 31;
    int warp = tid >> 5;
    int warpM = warp >> 2;       // 0..1
    int warpN = warp & 3;        // 0..3
    int g = lane >> 2;           // 0..7
    int qd = lane & 3;           // 0..3

    int aRow = tid >> 1;               // 0..127
    int aCol = (tid & 1) << 3;         // 0 or 8
    int aChunk = aCol >> 3;            // 0..1
    const float* Ap = A + (long)(by * 128 + aRow) * K + aCol;

    int bChunk = warp >> 2;            // 0..1
    int bQd = warp & 3;                // 0..3
    const float* Bbase = B + bx * 128 + lane;
    long bkOff = (long)(bChunk * 8 + bQd) * N;

    float acc[4][4][4];
    #pragma unroll
    for (int mt = 0; mt < 4; mt++)
        #pragma unroll
        for (int nt = 0; nt < 4; nt++)
            #pragma unroll
            for (int f = 0; f < 4; f++) acc[mt][nt][f] = 0.f;

    float av[8];
    float b0[4], b1[4];
    {
        float4 t0 = *(const float4*)(Ap);
        float4 t1 = *(const float4*)(Ap + 4);
        av[0]=t0.x; av[1]=t0.y; av[2]=t0.z; av[3]=t0.w;
        av[4]=t1.x; av[5]=t1.y; av[6]=t1.z; av[7]=t1.w;
        #pragma unroll
        for (int i = 0; i < 4; i++) {
            b0[i] = Bbase[bkOff + 32 * i];
            b1[i] = Bbase[bkOff + 4 * (long)N + 32 * i];
        }
    }

    for (int k0 = 0; k0 < K; k0 += 16) {
        #pragma unroll
        for (int j = 0; j < 4; j++) {
            float hf0, lf0, hf1, lf1;
            split2(av[j], hf0, lf0);
            split2(av[j + 4], hf1, lf1);
            PA[(aChunk * 128 + aRow) * 4 + j] = make_float4(hf0, lf0, hf1, lf1);
        }
        #pragma unroll
        for (int i = 0; i < 4; i++) {
            int n = lane + 32 * i;
            float hf0, lf0, hf1, lf1;
            split2(b0[i], hf0, lf0);
            split2(b1[i], hf1, lf1);
            PB[(bChunk * 128 + n) * 4 + bQd] = make_float4(hf0, lf0, hf1, lf1);
        }
        __syncthreads();

        int more = (k0 + 16) < K;
        if (more) {
            float4 t0 = *(const float4*)(Ap + k0 + 16);
            float4 t1 = *(const float4*)(Ap + k0 + 20);
            av[0]=t0.x; av[1]=t0.y; av[2]=t0.z; av[3]=t0.w;
            av[4]=t1.x; av[5]=t1.y; av[6]=t1.z; av[7]=t1.w;
            long ko = bkOff + (long)(k0 + 16) * N;
            #pragma unroll
            for (int i = 0; i < 4; i++) {
                b0[i] = Bbase[ko + 32 * i];
                b1[i] = Bbase[ko + 4 * (long)N + 32 * i];
            }
        }

        #pragma unroll
        for (int c = 0; c < 2; c++) {
            unsigned bh[4][2], bl[4][2];
            #pragma unroll
            for (int nt = 0; nt < 4; nt++) {
                float4 vb = PB[(c * 128 + warpN * 32 + nt * 8 + g) * 4 + qd];
                bh[nt][0] = __float_as_uint(vb.x);
                bl[nt][0] = __float_as_uint(vb.y);
                bh[nt][1] = __float_as_uint(vb.z);
                bl[nt][1] = __float_as_uint(vb.w);
            }
            #pragma unroll
            for (int mt = 0; mt < 4; mt++) {
                int m0 = warpM * 64 + mt * 16;
                float4 va0 = PA[(c * 128 + m0 + g) * 4 + qd];
                float4 va1 = PA[(c * 128 + m0 + g + 8) * 4 + qd];
                unsigned ah[4], al[4];
                ah[0] = __float_as_uint(va0.x); al[0] = __float_as_uint(va0.y);
                ah[1] = __float_as_uint(va1.x); al[1] = __float_as_uint(va1.y);
                ah[2] = __float_as_uint(va0.z); al[2] = __float_as_uint(va0.w);
                ah[3] = __float_as_uint(va1.z); al[3] = __float_as_uint(va1.w);
                #pragma unroll
                for (int nt = 0; nt < 4; nt++) {
                    mma8(acc[mt][nt], ah, bh[nt]);
                    mma8(acc[mt][nt], ah, bl[nt]);
                    mma8(acc[mt][nt], al, bh[nt]);
                }
            }
        }
        __syncthreads();
    }

    #pragma unroll
    for (int mt = 0; mt < 4; mt++) {
        int r0 = by * 128 + warpM * 64 + mt * 16 + g;
        int r1 = r0 + 8;
        #pragma unroll
        for (int nt = 0; nt < 4; nt++) {
            int col = bx * 128 + warpN * 32 + nt * 8 + 2 * qd;
            float bb0 = bias[col], bb1 = bias[col + 1];
            float v[4];
            v[0] = acc[mt][nt][0] + bb0;
            v[1] = acc[mt][nt][1] + bb1;
            v[2] = acc[mt][nt][2] + bb0;
            v[3] = acc[mt][nt][3] + bb1;
            if (fuse_gelu) {
                #pragma unroll
                for (int f = 0; f < 4; f++)
                    v[f] = 0.5f * v[f] * (1.0f + erff(v[f] * 0.70710678118654752440f));
            }
            *(float2*)(C + (long)r0 * N + col) = make_float2(v[0], v[1]);
            *(float2*)(C + (long)r1 * N + col) = make_float2(v[2], v[3]);
        }
    }
}

__global__ __launch_bounds__(256) void sgemm_kernel(
    const float* __restrict__ A, const float* __restrict__ B,
    const float* __restrict__ bias, float* __restrict__ C,
    int N, int K, int fuse_gelu)
{
    __shared__ float4 PA[1024];
    __shared__ float4 PB[1024];
    tf32_gemm_tile(A, B, bias, C, N, K, fuse_gelu, blockIdx.x, blockIdx.y, PA, PB);
}

// fused QKV + positional projections in ONE launch.
// z=0,1,2: C{q,k,v} = h @ W{q,k,v} over (6 x 32) tiles
// z=3: posk = rel_emb @ Wk ; z=4: posq = rel_emb @ Wq over (6 x 4) tiles (by>=4 exits)
__global__ __launch_bounds__(256) void sgemm_qkvpos_kernel(
    const float* __restrict__ h, const float* __restrict__ rel,
    const float* __restrict__ Wq, const float* __restrict__ Wk, const float* __restrict__ Wv,
    const float* __restrict__ bq, const float* __restrict__ bk, const float* __restrict__ bv,
    float* __restrict__ Cq, float* __restrict__ Ck, float* __restrict__ Cv,
    float* __restrict__ Pk, float* __restrict__ Pq)
{
    __shared__ float4 PA[1024];
    __shared__ float4 PB[1024];
    int z = blockIdx.z;
    const float* A;
    const float* W;
    const float* bb;
    float* C;
    if (z < 3) {
        A = h;
        W = (z == 0) ? Wq : (z == 1) ? Wk : Wv;
        bb = (z == 0) ? bq : (z == 1) ? bk : bv;
        C = (z == 0) ? Cq : (z == 1) ? Ck : Cv;
    } else {
        if (blockIdx.y >= TSPAN / 128) return;   // uniform per-CTA exit
        A = rel;
        W = (z == 3) ? Wk : Wq;
        bb = (z == 3) ? bk : bq;
        C = (z == 3) ? Pk : Pq;
    }
    tf32_gemm_tile(A, W, bb, C, HID, HID, 0, blockIdx.x, blockIdx.y, PA, PB);
}

// ---------------- NT GEMM (C = A @ B^T) via 3xTF32, both operands [row][k] -----------
// A[m][k] stride lda, B[n][k] stride ldb, C[m][n] stride ldc. Same fragment mapping
// as tf32_gemm_tile; B uses the A-style loader (rows are n).
__device__ __forceinline__ void tf32_gemm_nt_tile(
    const float* __restrict__ A, const float* __restrict__ B, float* __restrict__ C,
    int lda, int ldb, int ldc, int K, int bx, int by,
    float4* PA, float4* PB)
{
    int tid = threadIdx.x;
    int lane = tid & 31;
    int warp = tid >> 5;
    int warpM = warp >> 2;
    int warpN = warp & 3;
    int g = lane >> 2;
    int qd = lane & 3;

    int row = tid >> 1;                // 0..127
    int kc  = (tid & 1) << 3;          // 0 or 8
    int chunk = kc >> 3;               // 0..1
    const float* Ap = A + (long)(by * 128 + row) * lda + kc;
    const float* Bp = B + (long)(bx * 128 + row) * ldb + kc;

    float acc[4][4][4];
    #pragma unroll
    for (int mt = 0; mt < 4; mt++)
        #pragma unroll
        for (int nt = 0; nt < 4; nt++)
            #pragma unroll
            for (int f = 0; f < 4; f++) acc[mt][nt][f] = 0.f;

    float av[8], bv[8];
    {
        float4 t0 = *(const float4*)(Ap);
        float4 t1 = *(const float4*)(Ap + 4);
        av[0]=t0.x; av[1]=t0.y; av[2]=t0.z; av[3]=t0.w;
        av[4]=t1.x; av[5]=t1.y; av[6]=t1.z; av[7]=t1.w;
        float4 u0 = *(const float4*)(Bp);
        float4 u1 = *(const float4*)(Bp + 4);
        bv[0]=u0.x; bv[1]=u0.y; bv[2]=u0.z; bv[3]=u0.w;
        bv[4]=u1.x; bv[5]=u1.y; bv[6]=u1.z; bv[7]=u1.w;
    }

    for (int k0 = 0; k0 < K; k0 += 16) {
        #pragma unroll
        for (int j = 0; j < 4; j++) {
            float hf0, lf0, hf1, lf1;
            split2(av[j], hf0, lf0);
            split2(av[j + 4], hf1, lf1);
            PA[(chunk * 128 + row) * 4 + j] = make_float4(hf0, lf0, hf1, lf1);
            split2(bv[j], hf0, lf0);
            split2(bv[j + 4], hf1, lf1);
            PB[(chunk * 128 + row) * 4 + j] = make_float4(hf0, lf0, hf1, lf1);
        }
        __syncthreads();

        int more = (k0 + 16) < K;
        if (more) {
            float4 t0 = *(const float4*)(Ap + k0 + 16);
            float4 t1 = *(const float4*)(Ap + k0 + 20);
            av[0]=t0.x; av[1]=t0.y; av[2]=t0.z; av[3]=t0.w;
            av[4]=t1.x; av[5]=t1.y; av[6]=t1.z; av[7]=t1.w;
            float4 u0 = *(const float4*)(Bp + k0 + 16);
            float4 u1 = *(const float4*)(Bp + k0 + 20);
            bv[0]=u0.x; bv[1]=u0.y; bv[2]=u0.z; bv[3]=u0.w;
            bv[4]=u1.x; bv[5]=u1.y; bv[6]=u1.z; bv[7]=u1.w;
        }

        #pragma unroll
        for (int c = 0; c < 2; c++) {
            unsigned bh[4][2], bl[4][2];
            #pragma unroll
            for (int nt = 0; nt < 4; nt++) {
                float4 vb = PB[(c * 128 + warpN * 32 + nt * 8 + g) * 4 + qd];
                bh[nt][0] = __float_as_uint(vb.x);
                bl[nt][0] = __float_as_uint(vb.y);
                bh[nt][1] = __float_as_uint(vb.z);
                bl[nt][1] = __float_as_uint(vb.w);
            }
            #pragma unroll
            for (int mt = 0; mt < 4; mt++) {
                int m0 = warpM * 64 + mt * 16;
                float4 va0 = PA[(c * 128 + m0 + g) * 4 + qd];
                float4 va1 = PA[(c * 128 + m0 + g + 8) * 4 + qd];
                unsigned ah[4], al[4];
                ah[0] = __float_as_uint(va0.x); al[0] = __float_as_uint(va0.y);
                ah[1] = __float_as_uint(va1.x); al[1] = __float_as_uint(va1.y);
                ah[2] = __float_as_uint(va0.z); al[2] = __float_as_uint(va0.w);
                ah[3] = __float_as_uint(va1.z); al[3] = __float_as_uint(va1.w);
                #pragma unroll
                for (int nt = 0; nt < 4; nt++) {
                    mma8(acc[mt][nt], ah, bh[nt]);
                    mma8(acc[mt][nt], ah, bl[nt]);
                    mma8(acc[mt][nt], al, bh[nt]);
                }
            }
        }
        __syncthreads();
    }

    #pragma unroll
    for (int mt = 0; mt < 4; mt++) {
        int r0 = by * 128 + warpM * 64 + mt * 16 + g;
        int r1 = r0 + 8;
        #pragma unroll
        for (int nt = 0; nt < 4; nt++) {
            int col = bx * 128 + warpN * 32 + nt * 8 + 2 * qd;
            *(float2*)(C + (long)r0 * ldc + col) = make_float2(acc[mt][nt][0], acc[mt][nt][1]);
            *(float2*)(C + (long)r1 * ldc + col) = make_float2(acc[mt][nt][2], acc[mt][nt][3]);
        }
    }
}

// ---------------- fused score GEMMs on tensor cores: C[i,j] = A_i . B_j over K=64 -----
//   mode 0: A = q[b,h],  B = k[b,h]   -> g_qk  [SEQ,SEQ]
//   mode 1: A = q[b,h],  B = posk[h]  -> g_c2p [SEQ,TSPAN]
//   mode 2: A = posq[h], B = k[b,h]   -> g_p2c [TSPAN,SEQ] (transposed p2c)
__global__ __launch_bounds__(256) void gemm_scores_kernel(
    const float* __restrict__ q, const float* __restrict__ k,
    const float* __restrict__ posk, const float* __restrict__ posq)
{
    const int NB = BATCH * NHEAD;
    int z = blockIdx.z;
    int mode = z / NB;
    int batch = z % NB;
    int b = batch / NHEAD, h = batch % NHEAD;

    const float* Ab;
    const float* Bb;
    float* Cb;
    if (mode == 0) {
        Ab = q + (long)b * SEQ * HID + h * DHEAD;
        Bb = k + (long)b * SEQ * HID + h * DHEAD;
        Cb = g_qk + (long)batch * SEQ * SEQ;
    } else if (mode == 1) {
        Ab = q + (long)b * SEQ * HID + h * DHEAD;
        Bb = posk + h * DHEAD;
        Cb = g_c2p + (long)batch * SEQ * TSPAN;
    } else {
        Ab = posq + h * DHEAD;
        Bb = k + (long)b * SEQ * HID + h * DHEAD;
        Cb = g_p2c + (long)batch * TSPAN * SEQ;
    }

    __shared__ float4 PA[1024];
    __shared__ float4 PB[1024];
    tf32_gemm_nt_tile(Ab, Bb, Cb, HID, HID, 512, DHEAD, blockIdx.x, blockIdx.y, PA, PB);
}

// ---------------- fused gather + mask + softmax (in place over g_qk) ----------------
// scores[q,k] = (qk[q,k] + c2p[q, idx] + p2cT[idx, k]) / sqrt(3*DH), idx = c2pidx[q,k]
__global__ __launch_bounds__(256) void softmax_kernel(const int* __restrict__ mask)
{
    int q = blockIdx.x, h = blockIdx.y, b = blockIdx.z;
    long base  = ((long)(b * NHEAD + h) * SEQ + q) * SEQ;
    long cbase = ((long)(b * NHEAD + h) * SEQ + q) * TSPAN;
    long pbase = (long)(b * NHEAD + h) * TSPAN * SEQ;
    int tid = threadIdx.x;
    const float invScale = 0.07216878364870322992f;  // 1/sqrt(3*DH)

    __shared__ float sred[8];
    __shared__ float s_max, s_sum;

    int mrow = mask[b * SEQ + q];
    float vals[2];
    int vmask[2];
    #pragma unroll
    for (int u = 0; u < 2; u++) {
        int k = tid + u * 256;
        int idx = g_c2pidx[q * SEQ + k];   // shared index (p2cidx = c2pidx^T)
        float s = g_qk[base + k]
                + g_c2p[cbase + idx]
                + g_p2c[pbase + (long)idx * SEQ + k];   // transposed p2c: coalesced in k
        s *= invScale;
        int valid = mrow && mask[b * SEQ + k];
        vmask[u] = valid;
        vals[u] = valid ? s : -3.402823466e38f;
    }

    float mx = fmaxf(vals[0], vals[1]);
    #pragma unroll
    for (int o = 16; o > 0; o >>= 1) mx = fmaxf(mx, __shfl_xor_sync(0xffffffffu, mx, o));
    if ((tid & 31) == 0) sred[tid >> 5] = mx;
    __syncthreads();
    if (tid == 0) {
        float t = sred[0];
        #pragma unroll
        for (int i = 1; i < 8; i++) t = fmaxf(t, sred[i]);
        s_max = t;
    }
    __syncthreads();
    mx = s_max;

    float p[2];
    float sum = 0.f;
    #pragma unroll
    for (int u = 0; u < 2; u++) {
        p[u] = vmask[u] ? expf(vals[u] - mx) : 0.f;
        sum += p[u];
    }
    #pragma unroll
    for (int o = 16; o > 0; o >>= 1) sum += __shfl_xor_sync(0xffffffffu, sum, o);
    if ((tid & 31) == 0) sred[tid >> 5] = sum;
    __syncthreads();
    if (tid == 0) {
        float t = 0.f;
        #pragma unroll
        for (int i = 0; i < 8; i++) t += sred[i];
        s_sum = t;
    }
    __syncthreads();
    float inv = s_sum > 0.f ? 1.0f / s_sum : 0.f;

    #pragma unroll
    for (int u = 0; u < 2; u++)
        g_qk[base + tid + u * 256] = p[u] * inv;
}

// ---------------- batched probs @ V:  O[b,h] = P[b,h] [S,S] @ V[b,h] [S,DH] ----------------
// 128x64 tile, 128 threads, 8x8 acc, K chunks of 16.
__global__ __launch_bounds__(128) void gemm_pv_kernel(
    const float* __restrict__ P, const float* __restrict__ V, float* __restrict__ O)
{
    int batch = blockIdx.z;
    int b = batch / NHEAD, h = batch % NHEAD;
    const float* Pb = P + (long)batch * SEQ * SEQ;
    const float* Vb = V + (long)b * SEQ * HID + h * DHEAD;
    float* Ob = O + (long)b * SEQ * HID + h * DHEAD;
    int by = blockIdx.x;

    __shared__ float Ps[16][132];
    __shared__ float Vs[16][68];
    int tid = threadIdx.x;
    int tx = tid & 7;
    int ty = tid >> 3;

    float acc[8][8];
    #pragma unroll
    for (int i = 0; i < 8; i++)
        #pragma unroll
        for (int j = 0; j < 8; j++) acc[i][j] = 0.f;

    for (int k0 = 0; k0 < SEQ; k0 += 16) {
        __syncthreads();
        #pragma unroll
        for (int it = 0; it < 4; it++) {
            int e = tid + 128 * it;
            int m = e >> 2;
            int kg = (e & 3) << 2;
            float4 p4 = *(const float4*)(Pb + (long)(by * 128 + m) * SEQ + k0 + kg);
            Ps[kg + 0][m] = p4.x; Ps[kg + 1][m] = p4.y;
            Ps[kg + 2][m] = p4.z; Ps[kg + 3][m] = p4.w;
        }
        #pragma unroll
        for (int it = 0; it < 2; it++) {
            int e = tid + 128 * it;
            int r = e >> 4;
            int cg = (e & 15) << 2;
            float4 v4 = *(const float4*)(Vb + (long)(k0 + r) * HID + cg);
            *(float4*)&Vs[r][cg] = v4;
        }
        __syncthreads();
        #pragma unroll
        for (int kk = 0; kk < 16; kk++) {
            float ar[8], br[8];
            *(float4*)(ar)     = *(const float4*)&Ps[kk][ty * 8];
            *(float4*)(ar + 4) = *(const float4*)&Ps[kk][ty * 8 + 4];
            *(float4*)(br)     = *(const float4*)&Vs[kk][tx * 8];
            *(float4*)(br + 4) = *(const float4*)&Vs[kk][tx * 8 + 4];
            #pragma unroll
            for (int i = 0; i < 8; i++)
                #pragma unroll
                for (int j = 0; j < 8; j++) acc[i][j] += ar[i] * br[j];
        }
    }

    #pragma unroll
    for (int i = 0; i < 8; i++) {
        int row = by * 128 + ty * 8 + i;
        #pragma unroll
        for (int jj = 0; jj < 8; jj += 4)
            *(float4*)(Ob + (long)row * HID + tx * 8 + jj) = *(float4*)&acc[i][jj];
    }
}

// ---------------- host orchestration ----------------
extern "C" void kernel_launch(void* const* d_in, const int* in_sizes, int n_in,
                              void* d_out, int out_size)
{
    const float* word_emb = (const float*)d_in[0];
    const float* pos_emb  = (const float*)d_in[1];
    const float* emb_ln_g = (const float*)d_in[2];
    const float* emb_ln_b = (const float*)d_in[3];
    const float* rel_emb  = (const float*)d_in[4];
    const float* Wq = (const float*)d_in[5];
    const float* bq = (const float*)d_in[6];
    const float* Wk = (const float*)d_in[7];
    const float* bk = (const float*)d_in[8];
    const float* Wv = (const float*)d_in[9];
    const float* bv = (const float*)d_in[10];
    const float* Wo = (const float*)d_in[11];
    const float* bo = (const float*)d_in[12];
    const float* ln1_g = (const float*)d_in[13];
    const float* ln1_b = (const float*)d_in[14];
    const float* Wi  = (const float*)d_in[15];
    const float* bi  = (const float*)d_in[16];
    const float* Wo2 = (const float*)d_in[17];
    const float* bo2 = (const float*)d_in[18];
    const float* ln2_g = (const float*)d_in[19];
    const float* ln2_b = (const float*)d_in[20];
    const int* input_ids = (const int*)d_in[21];
    const int* amask     = (const int*)d_in[22];
    float* out = (float*)d_out;

    float *p_h, *p_q, *p_k, *p_v, *p_tmp, *p_h1, *p_ctx, *p_ff, *p_qk, *p_posk, *p_posq;
    cudaGetSymbolAddress((void**)&p_h,   g_h);
    cudaGetSymbolAddress((void**)&p_q,   g_q);
    cudaGetSymbolAddress((void**)&p_k,   g_k);
    cudaGetSymbolAddress((void**)&p_v,   g_v);
    cudaGetSymbolAddress((void**)&p_tmp, g_tmp);
    cudaGetSymbolAddress((void**)&p_h1,  g_h1);
    cudaGetSymbolAddress((void**)&p_ctx, g_ctx);
    cudaGetSymbolAddress((void**)&p_ff,  g_ff);
    cudaGetSymbolAddress((void**)&p_qk,  g_qk);
    cudaGetSymbolAddress((void**)&p_posk, g_posk);
    cudaGetSymbolAddress((void**)&p_posq, g_posq);

    const int BS = BATCH * SEQ;  // 4096

    build_idx_kernel<<<(SEQ * SEQ + 255) / 256, 256>>>();
    embed_kernel<<<(BS * HID + 255) / 256, 256>>>(word_emb, pos_emb, input_ids, p_tmp);
    ln_kernel<<<BS, 256>>>(p_tmp, nullptr, emb_ln_g, emb_ln_b, amask, p_h);

    for (int l = 0; l < NLAYER; l++) {
        const float* Wq_l = Wq + (long)l * HID * HID;  const float* bq_l = bq + l * HID;
        const float* Wk_l = Wk + (long)l * HID * HID;  const float* bk_l = bk + l * HID;
        const float* Wv_l = Wv + (long)l * HID * HID;  const float* bv_l = bv + l * HID;
        const float* Wo_l = Wo + (long)l * HID * HID;  const float* bo_l = bo + l * HID;
        const float* Wi_l  = Wi  + (long)l * HID * FFDIM;  const float* bi_l  = bi  + l * FFDIM;
        const float* Wo2_l = Wo2 + (long)l * FFDIM * HID;  const float* bo2_l = bo2 + l * HID;

        // fused QKV + positional projections: one launch, 6 x 32 x 5 CTAs (z=3,4 use by<4)
        dim3 gQKV(HID / 128, BS / 128, 5);
        sgemm_qkvpos_kernel<<<gQKV, 256>>>(p_h, rel_emb, Wq_l, Wk_l, Wv_l,
                                           bq_l, bk_l, bv_l,
                                           p_q, p_k, p_v, p_posk, p_posq);

        // fused qk + c2p + p2c(transposed) score GEMMs on tensor cores: 4 x 4 x 288 CTAs
        dim3 gSc(4, 4, 3 * BATCH * NHEAD);
        gemm_scores_kernel<<<gSc, 256>>>(p_q, p_k, p_posk, p_posq);

        dim3 gSM(SEQ, NHEAD, BATCH);
        softmax_kernel<<<gSM, 256>>>(amask);

        dim3 gPV(4, 1, BATCH * NHEAD);
        gemm_pv_kernel<<<gPV, 128>>>(p_qk, p_v, p_ctx);

        dim3 gP(HID / 128, BS / 128);
        sgemm_kernel<<<gP, 256>>>(p_ctx, Wo_l, bo_l, p_tmp, HID, HID, 0);
        ln_kernel<<<BS, 256>>>(p_tmp, p_h, ln1_g + l * HID, ln1_b + l * HID, nullptr, p_h1);

        dim3 gFF(FFDIM / 128, BS / 128);     // (24, 32)
        sgemm_kernel<<<gFF, 256>>>(p_h1, Wi_l, bi_l, p_ff, FFDIM, HID, 1);

        dim3 gO2(HID / 128, BS / 128);       // (6, 32)
        sgemm_kernel<<<gO2, 256>>>(p_ff, Wo2_l, bo2_l, p_tmp, HID, FFDIM, 0);

        float* dst = (l == NLAYER - 1) ? out : p_h;
        ln_kernel<<<BS, 256>>>(p_tmp, p_h1, ln2_g + l * HID, ln2_b + l * HID, nullptr, dst);
    }
}